// round 8
// baseline (speedup 1.0000x reference)
#include <cuda_runtime.h>

#define CCH 32
#define HH 128
#define WW 128
#define NPTS 262144
#define PLANE_ELEMS (HH * WW * CCH)

typedef unsigned long long ull;

// Transposed triplanes: (plane, y, x, c) -- 6.3 MB, L2-resident
__device__ float g_tp[3 * PLANE_ELEMS];
// Sampled features in (b, c, pos) layout; MLP row r reads flat [r*32 .. r*32+31]
__device__ float g_sampled[4 * CCH * NPTS];   // 134 MB

// ---------------------------------------------------------------------------
// packed f32x2 helpers
// ---------------------------------------------------------------------------
__device__ __forceinline__ ull fma2(ull a, ull b, ull c) {
    ull d;
    asm("fma.rn.f32x2 %0, %1, %2, %3;" : "=l"(d) : "l"(a), "l"(b), "l"(c));
    return d;
}
__device__ __forceinline__ ull pack2(float lo, float hi) {
    ull r;
    asm("mov.b64 %0, {%1, %2};" : "=l"(r) : "f"(lo), "f"(hi));
    return r;
}
__device__ __forceinline__ void unpack2(ull v, float& lo, float& hi) {
    asm("mov.b64 {%0, %1}, %2;" : "=f"(lo), "=f"(hi) : "l"(v));
}

// ---------------------------------------------------------------------------
// K1: transpose (3*C, H, W) -> (3, H, W, C)
// ---------------------------------------------------------------------------
__global__ void transpose_kernel(const float* __restrict__ tri) {
    int t = blockIdx.x * blockDim.x + threadIdx.x;
    if (t >= 3 * HH * WW) return;
    int p  = t / (HH * WW);
    int yx = t - p * (HH * WW);
    const float* src = tri + (size_t)p * CCH * HH * WW + yx;
    float v[CCH];
#pragma unroll
    for (int c = 0; c < CCH; c++) v[c] = src[(size_t)c * HH * WW];
    float4* dst = (float4*)(g_tp + (size_t)t * CCH);
#pragma unroll
    for (int k = 0; k < 8; k++)
        dst[k] = make_float4(v[4*k], v[4*k+1], v[4*k+2], v[4*k+3]);
}

// ---------------------------------------------------------------------------
// K2: cooperative sampler (unchanged from R7, proven ~50us)
// ---------------------------------------------------------------------------
__device__ __forceinline__ void sample_plane_c(const float* __restrict__ plane,
                                               float gx, float gy, int s,
                                               float4& acc) {
    float x = (gx + 1.0f) * 0.5f * (WW - 1);
    float y = (gy + 1.0f) * 0.5f * (HH - 1);
    float x0f = floorf(x), y0f = floorf(y);
    float wx = x - x0f,   wy = y - y0f;
    int x0 = (int)x0f, y0 = (int)y0f;
    int x1 = x0 + 1,   y1 = y0 + 1;

    float vxa = (x0 >= 0 && x0 < WW) ? 1.0f : 0.0f;
    float vxb = (x1 >= 0 && x1 < WW) ? 1.0f : 0.0f;
    float vya = (y0 >= 0 && y0 < HH) ? 1.0f : 0.0f;
    float vyb = (y1 >= 0 && y1 < HH) ? 1.0f : 0.0f;

    int xa = min(max(x0, 0), WW - 1);
    int xb = min(max(x1, 0), WW - 1);
    int ya = min(max(y0, 0), HH - 1);
    int yb = min(max(y1, 0), HH - 1);

    float wxs[2] = {(1.0f - wx) * vxa, wx * vxb};
    float wys[2] = {(1.0f - wy) * vya, wy * vyb};
    int   xi[2]  = {xa, xb};
    int   yi[2]  = {ya, yb};

#pragma unroll
    for (int cy = 0; cy < 2; cy++) {
#pragma unroll
        for (int cx = 0; cx < 2; cx++) {
            float w = wxs[cx] * wys[cy];
            float4 v = __ldg((const float4*)(plane +
                         (size_t)(yi[cy] * WW + xi[cx]) * CCH) + s);
            acc.x = fmaf(w, v.x, acc.x);
            acc.y = fmaf(w, v.y, acc.y);
            acc.z = fmaf(w, v.z, acc.z);
            acc.w = fmaf(w, v.w, acc.w);
        }
    }
}

__global__ void __launch_bounds__(256)
sample_kernel(const float* __restrict__ coords) {
    __shared__ float st[32 * 33];
    int tid = threadIdx.x;
    int pl  = tid >> 3;
    int s   = tid & 7;
    int pbase = blockIdx.x * 32;
    int p = pbase + pl;

    float gx = __ldg(coords + 3 * p + 0);
    float gy = __ldg(coords + 3 * p + 1);
    float gz = __ldg(coords + 3 * p + 2);

    float4 acc = make_float4(0.0f, 0.0f, 0.0f, 0.0f);
    // split order: plane0 = feat_xy, plane1 = feat_yz, plane2 = feat_xz
    sample_plane_c(g_tp,                   gx, gy, s, acc);   // feat_xy(x, y)
    sample_plane_c(g_tp + 2 * PLANE_ELEMS, gx, gz, s, acc);   // feat_xz(x, z)
    sample_plane_c(g_tp +     PLANE_ELEMS, gy, gz, s, acc);   // feat_yz(y, z)

    float* row = st + pl * 33 + 4 * s;
    row[0] = acc.x; row[1] = acc.y; row[2] = acc.z; row[3] = acc.w;
    __syncthreads();

    int b       = pbase >> 18;
    int posBase = pbase & (NPTS - 1);
    float* outb = g_sampled + (size_t)b * CCH * NPTS + posBase;
#pragma unroll
    for (int i = 0; i < 4; i++) {
        int idx = tid + 256 * i;
        int c = idx >> 5;
        int q = idx & 31;
        outb[(size_t)c * NPTS + q] = st[q * 33 + c];
    }
}

// ---------------------------------------------------------------------------
// K3: tiled MLP 32 -> 128 -> 128 -> 4.
// 512 threads (16 warps = 4/SMSP for latency hiding), tile = 128 rows.
// Thread tile = 2 rows x 16 cols. Warp: half=wid>>3 (row half), cg=wid&7 (cols).
// ---------------------------------------------------------------------------
#define NROWS_TILE 128
#define OFF_W1T 0
#define OFF_W0T 16384
#define OFF_W2  20480
#define OFF_B0  20992
#define OFF_B1  21120
#define OFF_B2  21248
#define OFF_FT  21264
#define OFF_H0  25360
#define OFF_RED 41744
#define SMEM_FLOATS 45840

__global__ void __launch_bounds__(512, 1)
mlp_kernel(const float* __restrict__ w0, const float* __restrict__ b0,
           const float* __restrict__ w1, const float* __restrict__ b1,
           const float* __restrict__ w2, const float* __restrict__ b2,
           float* __restrict__ out, int total) {
    extern __shared__ float smem[];
    float* s_w1t = smem + OFF_W1T;
    float* s_w0t = smem + OFF_W0T;
    float* s_w2  = smem + OFF_W2;
    float* s_b0  = smem + OFF_B0;
    float* s_b1  = smem + OFF_B1;
    float* s_b2  = smem + OFF_B2;
    float* s_ft  = smem + OFF_FT;
    float* s_h0  = smem + OFF_H0;
    float* s_red = smem + OFF_RED;

    int tid = threadIdx.x;
    for (int i = tid; i < 16384; i += 512) s_w1t[i] = w1[(i & 127) * 128 + (i >> 7)];
    for (int i = tid; i < 4096;  i += 512) s_w0t[i] = w0[(i & 127) * 32  + (i >> 7)];
    if (tid < 512) s_w2[tid] = w2[tid];
    if (tid < 128) { s_b0[tid] = b0[tid]; s_b1[tid] = b1[tid]; }
    if (tid < 4)   { s_b2[tid] = b2[tid]; }
    __syncthreads();

    int lane = tid & 31;
    int wid  = tid >> 5;
    int half = wid >> 3;          // row half 0/1
    int cg   = wid & 7;           // col group 0..7
    int c0   = cg * 16;
    int r0   = 64 * half + 2 * lane;

    ull binit[8];
    {
        const ulonglong2* b1v = (const ulonglong2*)(s_b1 + c0);
#pragma unroll
        for (int i = 0; i < 4; i++) {
            ulonglong2 v = b1v[i];
            binit[2*i]   = v.x;
            binit[2*i+1] = v.y;
        }
    }

    int ntiles = total / NROWS_TILE;
    for (int tile = blockIdx.x; tile < ntiles; tile += gridDim.x) {
        int rowBase = tile * NROWS_TILE;

        // ---- stage feats transposed: s_ft[k*128 + row] ----
        {
            int row = tid >> 2;             // 0..127
            int k0  = (tid & 3) * 8;        // 0,8,16,24
            const float4* src =
                (const float4*)(g_sampled + (size_t)(rowBase + row) * 32 + k0);
#pragma unroll
            for (int q = 0; q < 2; q++) {
                float4 v = src[q];
                int k = k0 + 4*q;
                s_ft[(k+0)*128 + row] = v.x;
                s_ft[(k+1)*128 + row] = v.y;
                s_ft[(k+2)*128 + row] = v.z;
                s_ft[(k+3)*128 + row] = v.w;
            }
        }
        __syncthreads();

        // ---- phase1: h0 = relu(feats @ w0^T + b0) ----
        {
            ull acc[2][8];
#pragma unroll
            for (int r = 0; r < 2; r++)
#pragma unroll
                for (int p = 0; p < 8; p++) acc[r][p] = 0ull;

#pragma unroll 4
            for (int k = 0; k < 32; k++) {
                float2 a = *(const float2*)(s_ft + k*128 + r0);
                ull a0 = pack2(a.x, a.x), a1 = pack2(a.y, a.y);
                const ulonglong2* wv = (const ulonglong2*)(s_w0t + k*128 + c0);
#pragma unroll
                for (int i = 0; i < 4; i++) {
                    ulonglong2 w = wv[i];
                    acc[0][2*i]   = fma2(a0, w.x, acc[0][2*i]);
                    acc[0][2*i+1] = fma2(a0, w.y, acc[0][2*i+1]);
                    acc[1][2*i]   = fma2(a1, w.x, acc[1][2*i]);
                    acc[1][2*i+1] = fma2(a1, w.y, acc[1][2*i+1]);
                }
            }
            // bias + relu + store transposed to s_h0[c*128 + row]
#pragma unroll
            for (int p = 0; p < 8; p++) {
                int c = c0 + 2*p;
                float blo = s_b0[c], bhi = s_b0[c+1];
                float l0, h0v, l1, h1v;
                unpack2(acc[0][p], l0, h0v);
                unpack2(acc[1][p], l1, h1v);
                float2 vlo = make_float2(fmaxf(l0 + blo, 0.0f), fmaxf(l1 + blo, 0.0f));
                float2 vhi = make_float2(fmaxf(h0v + bhi, 0.0f), fmaxf(h1v + bhi, 0.0f));
                *(float2*)(s_h0 + c*128 + r0)     = vlo;
                *(float2*)(s_h0 + (c+1)*128 + r0) = vhi;
            }
        }
        __syncthreads();

        // ---- phase2: h1 = relu(h0 @ w1^T + b1) ----
        ull acc1[2][8];
#pragma unroll
        for (int r = 0; r < 2; r++)
#pragma unroll
            for (int p = 0; p < 8; p++) acc1[r][p] = binit[p];

#pragma unroll 4
        for (int k = 0; k < 128; k++) {
            float2 a = *(const float2*)(s_h0 + k*128 + r0);
            ull a0 = pack2(a.x, a.x), a1 = pack2(a.y, a.y);
            const ulonglong2* wv = (const ulonglong2*)(s_w1t + k*128 + c0);
#pragma unroll
            for (int i = 0; i < 4; i++) {
                ulonglong2 w = wv[i];
                acc1[0][2*i]   = fma2(a0, w.x, acc1[0][2*i]);
                acc1[0][2*i+1] = fma2(a0, w.y, acc1[0][2*i+1]);
                acc1[1][2*i]   = fma2(a1, w.x, acc1[1][2*i]);
                acc1[1][2*i+1] = fma2(a1, w.y, acc1[1][2*i+1]);
            }
        }

#pragma unroll
        for (int r = 0; r < 2; r++)
#pragma unroll
            for (int p = 0; p < 8; p++) {
                float l, h;
                unpack2(acc1[r][p], l, h);
                acc1[r][p] = pack2(fmaxf(l, 0.0f), fmaxf(h, 0.0f));
            }

        // ---- phase3: partial layer2 over this warp's 16 cols ----
        float part[2][4];
#pragma unroll
        for (int kk = 0; kk < 4; kk++) {
            const ulonglong2* w2v = (const ulonglong2*)(s_w2 + kk*128 + c0);
            ull wp[8];
#pragma unroll
            for (int i = 0; i < 4; i++) {
                ulonglong2 v = w2v[i];
                wp[2*i] = v.x; wp[2*i+1] = v.y;
            }
#pragma unroll
            for (int r = 0; r < 2; r++) {
                ull s0 = 0ull, s1 = 0ull;
#pragma unroll
                for (int p = 0; p < 4; p++) {
                    s0 = fma2(acc1[r][2*p],   wp[2*p],   s0);
                    s1 = fma2(acc1[r][2*p+1], wp[2*p+1], s1);
                }
                float a, b, c, d;
                unpack2(s0, a, b);
                unpack2(s1, c, d);
                part[r][kk] = (a + b) + (c + d);
            }
        }
#pragma unroll
        for (int r = 0; r < 2; r++)
            *(float4*)(s_red + (size_t)(cg*128 + r0 + r) * 4) =
                make_float4(part[r][0], part[r][1], part[r][2], part[r][3]);
        __syncthreads();

        // ---- reduce across 8 col groups, relu, permute, store ----
        if (tid < 128) {
            float o0 = s_b2[0], o1 = s_b2[1], o2 = s_b2[2], o3 = s_b2[3];
#pragma unroll
            for (int g = 0; g < 8; g++) {
                float4 v = *(const float4*)(s_red + (size_t)(g*128 + tid) * 4);
                o0 += v.x; o1 += v.y; o2 += v.z; o3 += v.w;
            }
            o0 = fmaxf(o0, 0.0f); o1 = fmaxf(o1, 0.0f);
            o2 = fmaxf(o2, 0.0f); o3 = fmaxf(o3, 0.0f);
            // raw = concat(net[...,1:4], net[...,0:1])
            ((float4*)out)[rowBase + tid] = make_float4(o1, o2, o3, o0);
        }
        __syncthreads();
    }
}

// ---------------------------------------------------------------------------
extern "C" void kernel_launch(void* const* d_in, const int* in_sizes, int n_in,
                              void* d_out, int out_size) {
    const float* coords = (const float*)d_in[0];
    const float* tri    = (const float*)d_in[1];
    const float* w0     = (const float*)d_in[2];
    const float* b0     = (const float*)d_in[3];
    const float* w1     = (const float*)d_in[4];
    const float* b1     = (const float*)d_in[5];
    const float* w2     = (const float*)d_in[6];
    const float* b2     = (const float*)d_in[7];
    float* out = (float*)d_out;

    int total = in_sizes[0] / 3;   // B * N points = MLP rows

    transpose_kernel<<<(3 * HH * WW + 127) / 128, 128>>>(tri);
    sample_kernel<<<total / 32, 256>>>(coords);

    int mlp_smem = SMEM_FLOATS * 4;   // ~179 KB dynamic shared
    cudaFuncSetAttribute(mlp_kernel,
                         cudaFuncAttributeMaxDynamicSharedMemorySize, mlp_smem);
    mlp_kernel<<<148, 512, mlp_smem>>>(w0, b0, w1, b1, w2, b2, out, total);
}

// round 10
// speedup vs baseline: 1.0458x; 1.0458x over previous
#include <cuda_runtime.h>

#define CCH 32
#define HH 128
#define WW 128
#define NPTS 262144
#define PLANE_ELEMS (HH * WW * CCH)

typedef unsigned long long ull;

// Transposed triplanes: (plane, y, x, c) -- 6.3 MB, L2-resident
__device__ float g_tp[3 * PLANE_ELEMS];
// Sampled features in (b, c, pos) layout; MLP row r reads flat [r*32 .. r*32+31]
__device__ float g_sampled[4 * CCH * NPTS];   // 134 MB

// ---------------------------------------------------------------------------
// packed f32x2 helpers
// ---------------------------------------------------------------------------
__device__ __forceinline__ ull fma2(ull a, ull b, ull c) {
    ull d;
    asm("fma.rn.f32x2 %0, %1, %2, %3;" : "=l"(d) : "l"(a), "l"(b), "l"(c));
    return d;
}
__device__ __forceinline__ ull pack2(float lo, float hi) {
    ull r;
    asm("mov.b64 %0, {%1, %2};" : "=l"(r) : "f"(lo), "f"(hi));
    return r;
}
__device__ __forceinline__ void unpack2(ull v, float& lo, float& hi) {
    asm("mov.b64 {%0, %1}, %2;" : "=f"(lo), "=f"(hi) : "l"(v));
}

// ---------------------------------------------------------------------------
// K1: transpose (3*C, H, W) -> (3, H, W, C)
// ---------------------------------------------------------------------------
__global__ void transpose_kernel(const float* __restrict__ tri) {
    int t = blockIdx.x * blockDim.x + threadIdx.x;
    if (t >= 3 * HH * WW) return;
    int p  = t / (HH * WW);
    int yx = t - p * (HH * WW);
    const float* src = tri + (size_t)p * CCH * HH * WW + yx;
    float v[CCH];
#pragma unroll
    for (int c = 0; c < CCH; c++) v[c] = src[(size_t)c * HH * WW];
    float4* dst = (float4*)(g_tp + (size_t)t * CCH);
#pragma unroll
    for (int k = 0; k < 8; k++)
        dst[k] = make_float4(v[4*k], v[4*k+1], v[4*k+2], v[4*k+3]);
}

// ---------------------------------------------------------------------------
// K2: cooperative sampler (unchanged from R7, proven ~50us)
// ---------------------------------------------------------------------------
__device__ __forceinline__ void sample_plane_c(const float* __restrict__ plane,
                                               float gx, float gy, int s,
                                               float4& acc) {
    float x = (gx + 1.0f) * 0.5f * (WW - 1);
    float y = (gy + 1.0f) * 0.5f * (HH - 1);
    float x0f = floorf(x), y0f = floorf(y);
    float wx = x - x0f,   wy = y - y0f;
    int x0 = (int)x0f, y0 = (int)y0f;
    int x1 = x0 + 1,   y1 = y0 + 1;

    float vxa = (x0 >= 0 && x0 < WW) ? 1.0f : 0.0f;
    float vxb = (x1 >= 0 && x1 < WW) ? 1.0f : 0.0f;
    float vya = (y0 >= 0 && y0 < HH) ? 1.0f : 0.0f;
    float vyb = (y1 >= 0 && y1 < HH) ? 1.0f : 0.0f;

    int xa = min(max(x0, 0), WW - 1);
    int xb = min(max(x1, 0), WW - 1);
    int ya = min(max(y0, 0), HH - 1);
    int yb = min(max(y1, 0), HH - 1);

    float wxs[2] = {(1.0f - wx) * vxa, wx * vxb};
    float wys[2] = {(1.0f - wy) * vya, wy * vyb};
    int   xi[2]  = {xa, xb};
    int   yi[2]  = {ya, yb};

#pragma unroll
    for (int cy = 0; cy < 2; cy++) {
#pragma unroll
        for (int cx = 0; cx < 2; cx++) {
            float w = wxs[cx] * wys[cy];
            float4 v = __ldg((const float4*)(plane +
                         (size_t)(yi[cy] * WW + xi[cx]) * CCH) + s);
            acc.x = fmaf(w, v.x, acc.x);
            acc.y = fmaf(w, v.y, acc.y);
            acc.z = fmaf(w, v.z, acc.z);
            acc.w = fmaf(w, v.w, acc.w);
        }
    }
}

__global__ void __launch_bounds__(256)
sample_kernel(const float* __restrict__ coords) {
    __shared__ float st[32 * 33];
    int tid = threadIdx.x;
    int pl  = tid >> 3;
    int s   = tid & 7;
    int pbase = blockIdx.x * 32;
    int p = pbase + pl;

    float gx = __ldg(coords + 3 * p + 0);
    float gy = __ldg(coords + 3 * p + 1);
    float gz = __ldg(coords + 3 * p + 2);

    float4 acc = make_float4(0.0f, 0.0f, 0.0f, 0.0f);
    // split order: plane0 = feat_xy, plane1 = feat_yz, plane2 = feat_xz
    sample_plane_c(g_tp,                   gx, gy, s, acc);   // feat_xy(x, y)
    sample_plane_c(g_tp + 2 * PLANE_ELEMS, gx, gz, s, acc);   // feat_xz(x, z)
    sample_plane_c(g_tp +     PLANE_ELEMS, gy, gz, s, acc);   // feat_yz(y, z)

    float* row = st + pl * 33 + 4 * s;
    row[0] = acc.x; row[1] = acc.y; row[2] = acc.z; row[3] = acc.w;
    __syncthreads();

    int b       = pbase >> 18;
    int posBase = pbase & (NPTS - 1);
    float* outb = g_sampled + (size_t)b * CCH * NPTS + posBase;
#pragma unroll
    for (int i = 0; i < 4; i++) {
        int idx = tid + 256 * i;
        int c = idx >> 5;
        int q = idx & 31;
        outb[(size_t)c * NPTS + q] = st[q * 33 + c];
    }
}

// ---------------------------------------------------------------------------
// K3: tiled MLP 32 -> 128 -> 128 -> 4.
// 512 threads (16 warps = 4/SMSP), tile = 128 rows.
// Thread tile = 4 rows x 8 cols: warp cg=wid owns cols [8*cg, 8*cg+8),
// lane owns rows [4*lane, 4*lane+4). Double-buffered feats staging.
// ---------------------------------------------------------------------------
#define NROWS_TILE 128
#define FT_STRIDE  132              // padded k-row stride (mult of 4, bank-spread)
#define OFF_W1T 0                   // 16384
#define OFF_W0T 16384               // 4096
#define OFF_W2  20480               // 512
#define OFF_B0  20992               // 128
#define OFF_B1  21120               // 128
#define OFF_B2  21248               // 16
#define OFF_FT0 21264               // 32*132 = 4224
#define OFF_FT1 25488               // 4224
#define OFF_H0  29712               // 16384
#define OFF_RED 46096               // 16*128*4 = 8192
#define SMEM_FLOATS 54288           // ~217 KB

__global__ void __launch_bounds__(512, 1)
mlp_kernel(const float* __restrict__ w0, const float* __restrict__ b0,
           const float* __restrict__ w1, const float* __restrict__ b1,
           const float* __restrict__ w2, const float* __restrict__ b2,
           float* __restrict__ out, int total) {
    extern __shared__ float smem[];
    float* s_w1t = smem + OFF_W1T;
    float* s_w0t = smem + OFF_W0T;
    float* s_w2  = smem + OFF_W2;
    float* s_b0  = smem + OFF_B0;
    float* s_b1  = smem + OFF_B1;
    float* s_b2  = smem + OFF_B2;
    float* s_h0  = smem + OFF_H0;
    float* s_red = smem + OFF_RED;
    float* s_ftb[2] = { smem + OFF_FT0, smem + OFF_FT1 };

    int tid = threadIdx.x;
    for (int i = tid; i < 16384; i += 512) s_w1t[i] = w1[(i & 127) * 128 + (i >> 7)];
    for (int i = tid; i < 4096;  i += 512) s_w0t[i] = w0[(i & 127) * 32  + (i >> 7)];
    s_w2[tid] = w2[tid];
    if (tid < 128) { s_b0[tid] = b0[tid]; s_b1[tid] = b1[tid]; }
    if (tid < 4)   { s_b2[tid] = b2[tid]; }
    __syncthreads();   // weights/biases visible before binit reads s_b1 (R9 bug fix)

    int lane = tid & 31;
    int cg   = tid >> 5;          // warp = col group 0..15
    int c0   = cg * 8;
    int r0   = 4 * lane;

    // staging map: 4 threads per row, 8 k each
    int srow = tid >> 2;
    int sk0  = (tid & 3) * 8;

    int ntiles = total / NROWS_TILE;
    int tile0  = blockIdx.x;
    int buf = 0;

    // stage first tile's feats
    if (tile0 < ntiles) {
        const float4* src =
            (const float4*)(g_sampled + (size_t)(tile0 * NROWS_TILE + srow) * 32 + sk0);
        float4 v0 = src[0], v1 = src[1];
        float* ft = s_ftb[0];
        ft[(sk0+0)*FT_STRIDE + srow] = v0.x;
        ft[(sk0+1)*FT_STRIDE + srow] = v0.y;
        ft[(sk0+2)*FT_STRIDE + srow] = v0.z;
        ft[(sk0+3)*FT_STRIDE + srow] = v0.w;
        ft[(sk0+4)*FT_STRIDE + srow] = v1.x;
        ft[(sk0+5)*FT_STRIDE + srow] = v1.y;
        ft[(sk0+6)*FT_STRIDE + srow] = v1.z;
        ft[(sk0+7)*FT_STRIDE + srow] = v1.w;
    }

    ull binit[4];
    {
        // bias pairs for this thread's 8 cols (b1)
        const ulonglong2* b1v = (const ulonglong2*)(s_b1 + c0);
        ulonglong2 v0 = b1v[0], v1 = b1v[1];
        binit[0] = v0.x; binit[1] = v0.y; binit[2] = v1.x; binit[3] = v1.y;
    }

    for (int tile = tile0; tile < ntiles; tile += gridDim.x) {
        int rowBase = tile * NROWS_TILE;
        __syncthreads();   // staged feats visible; s_red from prev tile consumed

        const float* ft = s_ftb[buf];

        // ---- phase1 accumulate: h0 partial = feats @ w0^T ----
        ull acc[4][4];
#pragma unroll
        for (int r = 0; r < 4; r++)
#pragma unroll
            for (int p = 0; p < 4; p++) acc[r][p] = 0ull;

#pragma unroll 4
        for (int k = 0; k < 32; k++) {
            float4 a = *(const float4*)(ft + k*FT_STRIDE + r0);
            ull a0 = pack2(a.x, a.x), a1 = pack2(a.y, a.y);
            ull a2 = pack2(a.z, a.z), a3 = pack2(a.w, a.w);
            const ulonglong2* wv = (const ulonglong2*)(s_w0t + k*128 + c0);
            ulonglong2 wA = wv[0], wB = wv[1];
            acc[0][0] = fma2(a0, wA.x, acc[0][0]);
            acc[0][1] = fma2(a0, wA.y, acc[0][1]);
            acc[0][2] = fma2(a0, wB.x, acc[0][2]);
            acc[0][3] = fma2(a0, wB.y, acc[0][3]);
            acc[1][0] = fma2(a1, wA.x, acc[1][0]);
            acc[1][1] = fma2(a1, wA.y, acc[1][1]);
            acc[1][2] = fma2(a1, wB.x, acc[1][2]);
            acc[1][3] = fma2(a1, wB.y, acc[1][3]);
            acc[2][0] = fma2(a2, wA.x, acc[2][0]);
            acc[2][1] = fma2(a2, wA.y, acc[2][1]);
            acc[2][2] = fma2(a2, wB.x, acc[2][2]);
            acc[2][3] = fma2(a2, wB.y, acc[2][3]);
            acc[3][0] = fma2(a3, wA.x, acc[3][0]);
            acc[3][1] = fma2(a3, wA.y, acc[3][1]);
            acc[3][2] = fma2(a3, wB.x, acc[3][2]);
            acc[3][3] = fma2(a3, wB.y, acc[3][3]);
        }

        // ---- prefetch next tile's feats into registers ----
        int nextTile = tile + gridDim.x;
        float4 pv0, pv1;
        bool havePrefetch = (nextTile < ntiles);
        if (havePrefetch) {
            const float4* src =
                (const float4*)(g_sampled + (size_t)(nextTile * NROWS_TILE + srow) * 32 + sk0);
            pv0 = src[0]; pv1 = src[1];
        }

        // ---- epilogue1: bias + relu, store transposed to s_h0[c*128 + row] ----
#pragma unroll
        for (int p = 0; p < 4; p++) {
            int c = c0 + 2*p;
            float blo = s_b0[c], bhi = s_b0[c+1];
            float lo[4], hi[4];
#pragma unroll
            for (int r = 0; r < 4; r++) {
                float l, h;
                unpack2(acc[r][p], l, h);
                lo[r] = fmaxf(l + blo, 0.0f);
                hi[r] = fmaxf(h + bhi, 0.0f);
            }
            *(float4*)(s_h0 + c*128 + r0)     = make_float4(lo[0], lo[1], lo[2], lo[3]);
            *(float4*)(s_h0 + (c+1)*128 + r0) = make_float4(hi[0], hi[1], hi[2], hi[3]);
        }

        // ---- store prefetched feats into the other buffer ----
        if (havePrefetch) {
            float* ftn = s_ftb[buf ^ 1];
            ftn[(sk0+0)*FT_STRIDE + srow] = pv0.x;
            ftn[(sk0+1)*FT_STRIDE + srow] = pv0.y;
            ftn[(sk0+2)*FT_STRIDE + srow] = pv0.z;
            ftn[(sk0+3)*FT_STRIDE + srow] = pv0.w;
            ftn[(sk0+4)*FT_STRIDE + srow] = pv1.x;
            ftn[(sk0+5)*FT_STRIDE + srow] = pv1.y;
            ftn[(sk0+6)*FT_STRIDE + srow] = pv1.z;
            ftn[(sk0+7)*FT_STRIDE + srow] = pv1.w;
        }
        __syncthreads();   // s_h0 ready

        // ---- phase2: h1 = relu(h0 @ w1^T + b1) ----
        ull acc1[4][4];
#pragma unroll
        for (int r = 0; r < 4; r++)
#pragma unroll
            for (int p = 0; p < 4; p++) acc1[r][p] = binit[p];

#pragma unroll 4
        for (int k = 0; k < 128; k++) {
            float4 a = *(const float4*)(s_h0 + k*128 + r0);
            ull a0 = pack2(a.x, a.x), a1 = pack2(a.y, a.y);
            ull a2 = pack2(a.z, a.z), a3 = pack2(a.w, a.w);
            const ulonglong2* wv = (const ulonglong2*)(s_w1t + k*128 + c0);
            ulonglong2 wA = wv[0], wB = wv[1];
            acc1[0][0] = fma2(a0, wA.x, acc1[0][0]);
            acc1[0][1] = fma2(a0, wA.y, acc1[0][1]);
            acc1[0][2] = fma2(a0, wB.x, acc1[0][2]);
            acc1[0][3] = fma2(a0, wB.y, acc1[0][3]);
            acc1[1][0] = fma2(a1, wA.x, acc1[1][0]);
            acc1[1][1] = fma2(a1, wA.y, acc1[1][1]);
            acc1[1][2] = fma2(a1, wB.x, acc1[1][2]);
            acc1[1][3] = fma2(a1, wB.y, acc1[1][3]);
            acc1[2][0] = fma2(a2, wA.x, acc1[2][0]);
            acc1[2][1] = fma2(a2, wA.y, acc1[2][1]);
            acc1[2][2] = fma2(a2, wB.x, acc1[2][2]);
            acc1[2][3] = fma2(a2, wB.y, acc1[2][3]);
            acc1[3][0] = fma2(a3, wA.x, acc1[3][0]);
            acc1[3][1] = fma2(a3, wA.y, acc1[3][1]);
            acc1[3][2] = fma2(a3, wB.x, acc1[3][2]);
            acc1[3][3] = fma2(a3, wB.y, acc1[3][3]);
        }

        // relu h1 (repack)
#pragma unroll
        for (int r = 0; r < 4; r++)
#pragma unroll
            for (int p = 0; p < 4; p++) {
                float l, h;
                unpack2(acc1[r][p], l, h);
                acc1[r][p] = pack2(fmaxf(l, 0.0f), fmaxf(h, 0.0f));
            }

        // ---- phase3: partial layer2 over this warp's 8 cols ----
        float part[4][4];
#pragma unroll
        for (int kk = 0; kk < 4; kk++) {
            const ulonglong2* w2v = (const ulonglong2*)(s_w2 + kk*128 + c0);
            ulonglong2 wA = w2v[0], wB = w2v[1];
#pragma unroll
            for (int r = 0; r < 4; r++) {
                ull s0 = fma2(acc1[r][0], wA.x, 0ull);
                ull s1 = fma2(acc1[r][1], wA.y, 0ull);
                s0 = fma2(acc1[r][2], wB.x, s0);
                s1 = fma2(acc1[r][3], wB.y, s1);
                float a, b, c, d;
                unpack2(s0, a, b);
                unpack2(s1, c, d);
                part[r][kk] = (a + b) + (c + d);
            }
        }
#pragma unroll
        for (int r = 0; r < 4; r++)
            *(float4*)(s_red + (size_t)(cg*128 + r0 + r) * 4) =
                make_float4(part[r][0], part[r][1], part[r][2], part[r][3]);
        __syncthreads();

        // ---- reduce across 16 col groups, relu, permute, store ----
        if (tid < 128) {
            float o0 = s_b2[0], o1 = s_b2[1], o2 = s_b2[2], o3 = s_b2[3];
#pragma unroll
            for (int g = 0; g < 16; g++) {
                float4 v = *(const float4*)(s_red + (size_t)(g*128 + tid) * 4);
                o0 += v.x; o1 += v.y; o2 += v.z; o3 += v.w;
            }
            o0 = fmaxf(o0, 0.0f); o1 = fmaxf(o1, 0.0f);
            o2 = fmaxf(o2, 0.0f); o3 = fmaxf(o3, 0.0f);
            // raw = concat(net[...,1:4], net[...,0:1])
            ((float4*)out)[rowBase + tid] = make_float4(o1, o2, o3, o0);
        }
        buf ^= 1;
    }
}

// ---------------------------------------------------------------------------
extern "C" void kernel_launch(void* const* d_in, const int* in_sizes, int n_in,
                              void* d_out, int out_size) {
    const float* coords = (const float*)d_in[0];
    const float* tri    = (const float*)d_in[1];
    const float* w0     = (const float*)d_in[2];
    const float* b0     = (const float*)d_in[3];
    const float* w1     = (const float*)d_in[4];
    const float* b1     = (const float*)d_in[5];
    const float* w2     = (const float*)d_in[6];
    const float* b2     = (const float*)d_in[7];
    float* out = (float*)d_out;

    int total = in_sizes[0] / 3;   // B * N points = MLP rows

    transpose_kernel<<<(3 * HH * WW + 127) / 128, 128>>>(tri);
    sample_kernel<<<total / 32, 256>>>(coords);

    int mlp_smem = SMEM_FLOATS * 4;   // ~217 KB dynamic shared
    cudaFuncSetAttribute(mlp_kernel,
                         cudaFuncAttributeMaxDynamicSharedMemorySize, mlp_smem);
    mlp_kernel<<<148, 512, mlp_smem>>>(w0, b0, w1, b1, w2, b2, out, total);
}